// round 6
// baseline (speedup 1.0000x reference)
#include <cuda_runtime.h>
#include <math.h>

#define N_NODES 10000
#define N_EDGES 640000
#define FDIM    128
#define TE      64      // edges (or nodes) per block
#define LDI     260     // smem stride for edge input tile (256 + 4 pad)
#define LDH     132     // smem stride for hidden tile (128 + 4 pad)
#define LDN     388     // smem stride for node input tile (384 + 4 pad)

// scratch for segment-sum aggregate (no cudaMalloc allowed)
__device__ float g_agg[N_NODES * FDIM];

typedef unsigned long long u64;

__device__ __forceinline__ float sigmoidf_(float x) { return 1.0f / (1.0f + __expf(-x)); }
__device__ __forceinline__ float softsignf_(float x) { return x / (1.0f + fabsf(x)); }

// packed fp32x2 FMA: d = a*b + d (Blackwell doubled-rate FP32 path)
__device__ __forceinline__ void ffma2(u64& d, u64 a, u64 b) {
    asm("fma.rn.f32x2 %0, %1, %2, %0;" : "+l"(d) : "l"(a), "l"(b));
}
__device__ __forceinline__ u64 pack2(float s) {
    u64 r; asm("mov.b64 %0, {%1, %1};" : "=l"(r) : "f"(s)); return r;
}
__device__ __forceinline__ void unpack2(u64 v, float& lo, float& hi) {
    asm("mov.b64 {%0, %1}, %2;" : "=f"(lo), "=f"(hi) : "l"(v));
}
// load 16B of weights straight into two b64 (f32x2) regs — no repack movs
__device__ __forceinline__ void ldg2x2(const float* p, u64& d0, u64& d1) {
    asm("ld.global.nc.v2.b64 {%0, %1}, [%2];" : "=l"(d0), "=l"(d1) : "l"(p));
}

// ---------------------------------------------------------------------------
// Edge kernel: gather -> sigmoid([src,dst]@Wm1+bm1) -> softsign(h@Wm2+bm2)
//              -> atomic scatter-add into g_agg[rows]
// Block: 64 edges x 128 outputs, 256 threads.
// Thread (tx in [0,16): 8 outputs, ty in [0,16): 4 edges) -> 16 f32x2 accs.
// ---------------------------------------------------------------------------
__global__ void __launch_bounds__(256, 2)
edge_kernel(const float* __restrict__ features,
            const int*   __restrict__ rows,
            const int*   __restrict__ cols,
            const float* __restrict__ Wm1,
            const float* __restrict__ bm1,
            const float* __restrict__ Wm2,
            const float* __restrict__ bm2)
{
    extern __shared__ float smem[];
    float* sIn  = smem;                          // TE x LDI floats
    int*   sRow = (int*)(smem + TE * LDI);       // TE
    int*   sCol = sRow + TE;                     // TE

    const int tid = threadIdx.x;
    const int tx  = tid & 15;        // output octet: cols [tx*8, tx*8+8)
    const int ty  = tid >> 4;        // edge quad:   rows [ty*4, ty*4+4)
    const int e0  = blockIdx.x * TE;

    if (tid < TE) { sRow[tid] = rows[e0 + tid]; sCol[tid] = cols[e0 + tid]; }
    __syncthreads();

    // Gather 64 edges x 256 floats = 4096 float4; 16 per thread, coalesced.
    // Streaming loads keep L1 free for the weights.
    #pragma unroll
    for (int i = 0; i < 16; i++) {
        int idx = tid + i * 256;
        int e = idx >> 6;
        int q = idx & 63;                 // float4 index within [src|dst] row
        const float* base = (q < 32)
            ? features + (size_t)sRow[e] * FDIM + q * 4
            : features + (size_t)sCol[e] * FDIM + (q - 32) * 4;
        float4 v = __ldcs((const float4*)base);
        *(float4*)&sIn[e * LDI + q * 4] = v;   // q*4: dst half lands at +FDIM
    }
    __syncthreads();

    // ---- GEMM1: [64,256] @ Wm1[256,128], packed f32x2 ----
    u64 acc[4][4];
    #pragma unroll
    for (int e = 0; e < 4; e++)
        #pragma unroll
        for (int j = 0; j < 4; j++) acc[e][j] = 0ull;

    const float* aBase = sIn + (ty * 4) * LDI;
    const float* wBase = Wm1 + tx * 8;

    #pragma unroll 1
    for (int k = 0; k < 2 * FDIM; k += 4) {
        u64 w[4][4];
        #pragma unroll
        for (int kk = 0; kk < 4; kk++) {
            const float* wp = wBase + (k + kk) * FDIM;
            ldg2x2(wp,     w[kk][0], w[kk][1]);
            ldg2x2(wp + 4, w[kk][2], w[kk][3]);
        }
        #pragma unroll
        for (int e = 0; e < 4; e++) {
            float4 a = *(const float4*)(aBase + e * LDI + k);
            u64 a0 = pack2(a.x), a1 = pack2(a.y), a2 = pack2(a.z), a3 = pack2(a.w);
            #pragma unroll
            for (int j = 0; j < 4; j++) {
                ffma2(acc[e][j], a0, w[0][j]);
                ffma2(acc[e][j], a1, w[1][j]);
                ffma2(acc[e][j], a2, w[2][j]);
                ffma2(acc[e][j], a3, w[3][j]);
            }
        }
    }

    // ---- epilogue 1: h = sigmoid(acc + bm1) -> smem overlay ----
    float4 b1a = __ldg((const float4*)(bm1 + tx * 8));
    float4 b1b = __ldg((const float4*)(bm1 + tx * 8 + 4));
    float b1[8] = {b1a.x, b1a.y, b1a.z, b1a.w, b1b.x, b1b.y, b1b.z, b1b.w};
    __syncthreads();                       // readers of sIn done
    float* sH = smem;                      // TE x LDH, fits inside sIn footprint
    #pragma unroll
    for (int e = 0; e < 4; e++) {
        float h[8];
        #pragma unroll
        for (int j = 0; j < 4; j++) {
            float lo, hi; unpack2(acc[e][j], lo, hi);
            h[2 * j]     = sigmoidf_(lo + b1[2 * j]);
            h[2 * j + 1] = sigmoidf_(hi + b1[2 * j + 1]);
        }
        float* dst = &sH[(ty * 4 + e) * LDH + tx * 8];
        *(float4*)dst       = make_float4(h[0], h[1], h[2], h[3]);
        *(float4*)(dst + 4) = make_float4(h[4], h[5], h[6], h[7]);
    }
    __syncthreads();

    // ---- GEMM2: [64,128] @ Wm2[128,128], packed f32x2 ----
    u64 acc2[4][4];
    #pragma unroll
    for (int e = 0; e < 4; e++)
        #pragma unroll
        for (int j = 0; j < 4; j++) acc2[e][j] = 0ull;

    const float* hBase  = sH + (ty * 4) * LDH;
    const float* w2Base = Wm2 + tx * 8;

    #pragma unroll 1
    for (int k = 0; k < FDIM; k += 4) {
        u64 w[4][4];
        #pragma unroll
        for (int kk = 0; kk < 4; kk++) {
            const float* wp = w2Base + (k + kk) * FDIM;
            ldg2x2(wp,     w[kk][0], w[kk][1]);
            ldg2x2(wp + 4, w[kk][2], w[kk][3]);
        }
        #pragma unroll
        for (int e = 0; e < 4; e++) {
            float4 a = *(const float4*)(hBase + e * LDH + k);
            u64 a0 = pack2(a.x), a1 = pack2(a.y), a2 = pack2(a.z), a3 = pack2(a.w);
            #pragma unroll
            for (int j = 0; j < 4; j++) {
                ffma2(acc2[e][j], a0, w[0][j]);
                ffma2(acc2[e][j], a1, w[1][j]);
                ffma2(acc2[e][j], a2, w[2][j]);
                ffma2(acc2[e][j], a3, w[3][j]);
            }
        }
    }

    // ---- epilogue 2: softsign + coalesced atomic scatter-add ----
    float4 b2a = __ldg((const float4*)(bm2 + tx * 8));
    float4 b2b = __ldg((const float4*)(bm2 + tx * 8 + 4));
    float b2[8] = {b2a.x, b2a.y, b2a.z, b2a.w, b2b.x, b2b.y, b2b.z, b2b.w};
    #pragma unroll
    for (int e = 0; e < 4; e++) {
        int r = sRow[ty * 4 + e];
        float* dst = g_agg + (size_t)r * FDIM + tx * 8;
        #pragma unroll
        for (int j = 0; j < 4; j++) {
            float lo, hi; unpack2(acc2[e][j], lo, hi);
            atomicAdd(dst + 2 * j,     softsignf_(lo + b2[2 * j]));
            atomicAdd(dst + 2 * j + 1, softsignf_(hi + b2[2 * j + 1]));
        }
    }
}

// ---------------------------------------------------------------------------
// Node kernel: g = sigmoid([feat, agg, time]); g = sigmoid(g@Wf1+bf1);
//              out = softsign(g@Wf2+bf2)
// ---------------------------------------------------------------------------
__global__ void __launch_bounds__(256, 2)
node_kernel(const float* __restrict__ features,
            const float* __restrict__ time_emb,
            const float* __restrict__ Wf1,
            const float* __restrict__ bf1,
            const float* __restrict__ Wf2,
            const float* __restrict__ bf2,
            float* __restrict__ out)
{
    extern __shared__ float smem[];
    float* sIn = smem;   // TE x LDN floats

    const int tid  = threadIdx.x;
    const int lane = tid & 31;
    const int wrp  = tid >> 5;
    const int tx   = tid & 15;
    const int ty   = tid >> 4;
    const int n0   = blockIdx.x * TE;

    // Gather + first sigmoid during smem fill (warp-per-node layout)
    for (int n = wrp; n < TE; n += 8) {
        int node = n0 + n;
        float4 a, g, t;
        if (node < N_NODES) {
            a = __ldg((const float4*)(features + (size_t)node * FDIM) + lane);
            g = *((const float4*)(g_agg + (size_t)node * FDIM) + lane);
            t = __ldg((const float4*)(time_emb + (size_t)node * FDIM) + lane);
        } else {
            a = g = t = make_float4(0.f, 0.f, 0.f, 0.f);
        }
        *(float4*)&sIn[n * LDN + lane * 4] =
            make_float4(sigmoidf_(a.x), sigmoidf_(a.y), sigmoidf_(a.z), sigmoidf_(a.w));
        *(float4*)&sIn[n * LDN + FDIM + lane * 4] =
            make_float4(sigmoidf_(g.x), sigmoidf_(g.y), sigmoidf_(g.z), sigmoidf_(g.w));
        *(float4*)&sIn[n * LDN + 2 * FDIM + lane * 4] =
            make_float4(sigmoidf_(t.x), sigmoidf_(t.y), sigmoidf_(t.z), sigmoidf_(t.w));
    }
    __syncthreads();

    // ---- GEMM1: [64,384] @ Wf1[384,128], packed f32x2 ----
    u64 acc[4][4];
    #pragma unroll
    for (int e = 0; e < 4; e++)
        #pragma unroll
        for (int j = 0; j < 4; j++) acc[e][j] = 0ull;

    const float* aBase = sIn + (ty * 4) * LDN;
    const float* wBase = Wf1 + tx * 8;

    #pragma unroll 1
    for (int k = 0; k < 3 * FDIM; k += 4) {
        u64 w[4][4];
        #pragma unroll
        for (int kk = 0; kk < 4; kk++) {
            const float* wp = wBase + (k + kk) * FDIM;
            ldg2x2(wp,     w[kk][0], w[kk][1]);
            ldg2x2(wp + 4, w[kk][2], w[kk][3]);
        }
        #pragma unroll
        for (int e = 0; e < 4; e++) {
            float4 a = *(const float4*)(aBase + e * LDN + k);
            u64 a0 = pack2(a.x), a1 = pack2(a.y), a2 = pack2(a.z), a3 = pack2(a.w);
            #pragma unroll
            for (int j = 0; j < 4; j++) {
                ffma2(acc[e][j], a0, w[0][j]);
                ffma2(acc[e][j], a1, w[1][j]);
                ffma2(acc[e][j], a2, w[2][j]);
                ffma2(acc[e][j], a3, w[3][j]);
            }
        }
    }

    float4 b1a = __ldg((const float4*)(bf1 + tx * 8));
    float4 b1b = __ldg((const float4*)(bf1 + tx * 8 + 4));
    float b1[8] = {b1a.x, b1a.y, b1a.z, b1a.w, b1b.x, b1b.y, b1b.z, b1b.w};
    __syncthreads();
    float* sH = smem;
    #pragma unroll
    for (int e = 0; e < 4; e++) {
        float h[8];
        #pragma unroll
        for (int j = 0; j < 4; j++) {
            float lo, hi; unpack2(acc[e][j], lo, hi);
            h[2 * j]     = sigmoidf_(lo + b1[2 * j]);
            h[2 * j + 1] = sigmoidf_(hi + b1[2 * j + 1]);
        }
        float* dst = &sH[(ty * 4 + e) * LDH + tx * 8];
        *(float4*)dst       = make_float4(h[0], h[1], h[2], h[3]);
        *(float4*)(dst + 4) = make_float4(h[4], h[5], h[6], h[7]);
    }
    __syncthreads();

    // ---- GEMM2: [64,128] @ Wf2[128,128], packed f32x2 ----
    u64 acc2[4][4];
    #pragma unroll
    for (int e = 0; e < 4; e++)
        #pragma unroll
        for (int j = 0; j < 4; j++) acc2[e][j] = 0ull;

    const float* hBase  = sH + (ty * 4) * LDH;
    const float* w2Base = Wf2 + tx * 8;

    #pragma unroll 1
    for (int k = 0; k < FDIM; k += 4) {
        u64 w[4][4];
        #pragma unroll
        for (int kk = 0; kk < 4; kk++) {
            const float* wp = w2Base + (k + kk) * FDIM;
            ldg2x2(wp,     w[kk][0], w[kk][1]);
            ldg2x2(wp + 4, w[kk][2], w[kk][3]);
        }
        #pragma unroll
        for (int e = 0; e < 4; e++) {
            float4 a = *(const float4*)(hBase + e * LDH + k);
            u64 a0 = pack2(a.x), a1 = pack2(a.y), a2 = pack2(a.z), a3 = pack2(a.w);
            #pragma unroll
            for (int j = 0; j < 4; j++) {
                ffma2(acc2[e][j], a0, w[0][j]);
                ffma2(acc2[e][j], a1, w[1][j]);
                ffma2(acc2[e][j], a2, w[2][j]);
                ffma2(acc2[e][j], a3, w[3][j]);
            }
        }
    }

    float4 b2a = __ldg((const float4*)(bf2 + tx * 8));
    float4 b2b = __ldg((const float4*)(bf2 + tx * 8 + 4));
    float b2[8] = {b2a.x, b2a.y, b2a.z, b2a.w, b2b.x, b2b.y, b2b.z, b2b.w};
    #pragma unroll
    for (int e = 0; e < 4; e++) {
        int node = n0 + ty * 4 + e;
        if (node < N_NODES) {
            float o[8];
            #pragma unroll
            for (int j = 0; j < 4; j++) {
                float lo, hi; unpack2(acc2[e][j], lo, hi);
                o[2 * j]     = softsignf_(lo + b2[2 * j]);
                o[2 * j + 1] = softsignf_(hi + b2[2 * j + 1]);
            }
            float* dst = out + (size_t)node * FDIM + tx * 8;
            *(float4*)dst       = make_float4(o[0], o[1], o[2], o[3]);
            *(float4*)(dst + 4) = make_float4(o[4], o[5], o[6], o[7]);
        }
    }
}

extern "C" void kernel_launch(void* const* d_in, const int* in_sizes, int n_in,
                              void* d_out, int out_size)
{
    const float* features = (const float*)d_in[0];
    const int*   rows     = (const int*)  d_in[1];
    const int*   cols     = (const int*)  d_in[2];
    const float* time_emb = (const float*)d_in[3];
    const float* Wm1      = (const float*)d_in[4];
    const float* bm1      = (const float*)d_in[5];
    const float* Wm2      = (const float*)d_in[6];
    const float* bm2      = (const float*)d_in[7];
    const float* Wf1      = (const float*)d_in[8];
    const float* bf1      = (const float*)d_in[9];
    const float* Wf2      = (const float*)d_in[10];
    const float* bf2      = (const float*)d_in[11];
    float* out = (float*)d_out;

    const int edge_smem = TE * LDI * sizeof(float) + 2 * TE * sizeof(int); // 67072 B
    const int node_smem = TE * LDN * sizeof(float);                        // 99328 B
    cudaFuncSetAttribute(edge_kernel, cudaFuncAttributeMaxDynamicSharedMemorySize, edge_smem);
    cudaFuncSetAttribute(node_kernel, cudaFuncAttributeMaxDynamicSharedMemorySize, node_smem);

    void* aggp = nullptr;
    cudaGetSymbolAddress(&aggp, g_agg);
    cudaMemsetAsync(aggp, 0, (size_t)N_NODES * FDIM * sizeof(float));

    edge_kernel<<<N_EDGES / TE, 256, edge_smem>>>(features, rows, cols, Wm1, bm1, Wm2, bm2);
    node_kernel<<<(N_NODES + TE - 1) / TE, 256, node_smem>>>(features, time_emb,
                                                             Wf1, bf1, Wf2, bf2, out);
}

// round 7
// speedup vs baseline: 1.6586x; 1.6586x over previous
#include <cuda_runtime.h>
#include <math.h>

#define N_NODES 10000
#define N_EDGES 640000
#define FDIM    128
#define TE      64      // edges (or nodes) per block
#define LDI     260     // smem stride for edge input tile (256 + 4 pad)
#define LDH     132     // smem stride for hidden tile (128 + 4 pad)
#define LDN     388     // smem stride for node input tile (384 + 4 pad)

// scratch for segment-sum aggregate (no cudaMalloc allowed)
__device__ float g_agg[N_NODES * FDIM];

typedef unsigned long long u64;

__device__ __forceinline__ float sigmoidf_(float x) { return 1.0f / (1.0f + __expf(-x)); }
__device__ __forceinline__ float softsignf_(float x) { return x / (1.0f + fabsf(x)); }

// packed fp32x2 FMA: d = a*b + d (rounds .rn per lane — bit-identical to fmaf)
__device__ __forceinline__ void ffma2(u64& d, u64 a, u64 b) {
    asm("fma.rn.f32x2 %0, %1, %2, %0;" : "+l"(d) : "l"(a), "l"(b));
}
__device__ __forceinline__ u64 pack2(float s) {
    u64 r; asm("mov.b64 %0, {%1, %1};" : "=l"(r) : "f"(s)); return r;
}
__device__ __forceinline__ void unpack2(u64 v, float& lo, float& hi) {
    asm("mov.b64 {%0, %1}, %2;" : "=f"(lo), "=f"(hi) : "l"(v));
}
// 16B weight load straight into two b64 (f32x2) regs — no repack movs
__device__ __forceinline__ void ldg2x2(const float* p, u64& d0, u64& d1) {
    asm("ld.global.nc.v2.b64 {%0, %1}, [%2];" : "=l"(d0), "=l"(d1) : "l"(p));
}
// vector reduction: g_agg[addr..addr+1] += {v0,v1} (no return; FA3-style)
__device__ __forceinline__ void red2(float* p, float v0, float v1) {
    asm volatile("red.global.add.v2.f32 [%0], {%1, %2};" :: "l"(p), "f"(v0), "f"(v1) : "memory");
}

// ---------------------------------------------------------------------------
// Edge kernel: gather src/dst -> sigmoid([src,dst]@Wm1+bm1)
//              -> softsign(h@Wm2+bm2) -> red-scatter into g_agg[rows]
// R5 tiling (proven L1-lean): tx in [0,32) = output quad, ty in [0,8) = 8-edge
// group. Arithmetic upgraded to packed f32x2 (2 u64 accs per edge).
// ---------------------------------------------------------------------------
__global__ void __launch_bounds__(256, 2)
edge_kernel(const float* __restrict__ features,
            const int*   __restrict__ rows,
            const int*   __restrict__ cols,
            const float* __restrict__ Wm1,
            const float* __restrict__ bm1,
            const float* __restrict__ Wm2,
            const float* __restrict__ bm2)
{
    extern __shared__ float smem[];
    float* sIn  = smem;                          // TE x LDI floats
    int*   sRow = (int*)(smem + TE * LDI);       // TE
    int*   sCol = sRow + TE;                     // TE

    const int tid = threadIdx.x;
    const int tx  = tid & 31;        // lane: output quad index
    const int ty  = tid >> 5;        // warp: edge group
    const int e0  = blockIdx.x * TE;

    if (tid < TE) { sRow[tid] = rows[e0 + tid]; sCol[tid] = cols[e0 + tid]; }
    __syncthreads();

    // Gather: one warp per edge (8 edges per warp), lane covers 4 floats.
    for (int e = ty; e < TE; e += 8) {
        const float4* sp = (const float4*)(features + (size_t)sRow[e] * FDIM);
        const float4* dp = (const float4*)(features + (size_t)sCol[e] * FDIM);
        float4 s = __ldcs(sp + tx);
        float4 d = __ldcs(dp + tx);
        *(float4*)&sIn[e * LDI + tx * 4]        = s;
        *(float4*)&sIn[e * LDI + FDIM + tx * 4] = d;
    }
    __syncthreads();

    // ---- GEMM1: [64,256] @ Wm1[256,128], packed f32x2 ----
    u64 acc[8][2];
    #pragma unroll
    for (int e = 0; e < 8; e++) { acc[e][0] = 0ull; acc[e][1] = 0ull; }

    const float* wBase = Wm1 + tx * 4;
    const float* aBase = sIn + (ty * 8) * LDI;

    #pragma unroll 2
    for (int k = 0; k < 2 * FDIM; k += 4) {
        u64 w0a, w0b, w1a, w1b, w2a, w2b, w3a, w3b;
        ldg2x2(wBase + (k + 0) * FDIM, w0a, w0b);
        ldg2x2(wBase + (k + 1) * FDIM, w1a, w1b);
        ldg2x2(wBase + (k + 2) * FDIM, w2a, w2b);
        ldg2x2(wBase + (k + 3) * FDIM, w3a, w3b);
        #pragma unroll
        for (int e = 0; e < 8; e++) {
            float4 a = *(const float4*)(aBase + e * LDI + k);
            u64 a0 = pack2(a.x), a1 = pack2(a.y), a2 = pack2(a.z), a3 = pack2(a.w);
            ffma2(acc[e][0], a0, w0a); ffma2(acc[e][1], a0, w0b);
            ffma2(acc[e][0], a1, w1a); ffma2(acc[e][1], a1, w1b);
            ffma2(acc[e][0], a2, w2a); ffma2(acc[e][1], a2, w2b);
            ffma2(acc[e][0], a3, w3a); ffma2(acc[e][1], a3, w3b);
        }
    }
    __syncthreads();   // everyone done reading sIn before H overlays it

    // ---- epilogue 1: h = sigmoid(acc + bm1) -> smem overlay ----
    float4 b1 = __ldg((const float4*)bm1 + tx);
    float* sH = smem;  // TE x LDH floats, fits inside the sIn footprint
    #pragma unroll
    for (int e = 0; e < 8; e++) {
        float x0, x1, x2, x3;
        unpack2(acc[e][0], x0, x1);
        unpack2(acc[e][1], x2, x3);
        float4 h;
        h.x = sigmoidf_(x0 + b1.x);
        h.y = sigmoidf_(x1 + b1.y);
        h.z = sigmoidf_(x2 + b1.z);
        h.w = sigmoidf_(x3 + b1.w);
        *(float4*)&sH[(ty * 8 + e) * LDH + tx * 4] = h;
    }
    __syncthreads();

    // ---- GEMM2: [64,128] @ Wm2[128,128], packed f32x2 ----
    u64 acc2[8][2];
    #pragma unroll
    for (int e = 0; e < 8; e++) { acc2[e][0] = 0ull; acc2[e][1] = 0ull; }

    const float* w2Base = Wm2 + tx * 4;
    const float* hBase  = sH + (ty * 8) * LDH;

    #pragma unroll 2
    for (int k = 0; k < FDIM; k += 4) {
        u64 w0a, w0b, w1a, w1b, w2a, w2b, w3a, w3b;
        ldg2x2(w2Base + (k + 0) * FDIM, w0a, w0b);
        ldg2x2(w2Base + (k + 1) * FDIM, w1a, w1b);
        ldg2x2(w2Base + (k + 2) * FDIM, w2a, w2b);
        ldg2x2(w2Base + (k + 3) * FDIM, w3a, w3b);
        #pragma unroll
        for (int e = 0; e < 8; e++) {
            float4 a = *(const float4*)(hBase + e * LDH + k);
            u64 a0 = pack2(a.x), a1 = pack2(a.y), a2 = pack2(a.z), a3 = pack2(a.w);
            ffma2(acc2[e][0], a0, w0a); ffma2(acc2[e][1], a0, w0b);
            ffma2(acc2[e][0], a1, w1a); ffma2(acc2[e][1], a1, w1b);
            ffma2(acc2[e][0], a2, w2a); ffma2(acc2[e][1], a2, w2b);
            ffma2(acc2[e][0], a3, w3a); ffma2(acc2[e][1], a3, w3b);
        }
    }

    // ---- epilogue 2: softsign + vector red scatter-add ----
    float4 b2 = __ldg((const float4*)bm2 + tx);
    #pragma unroll
    for (int e = 0; e < 8; e++) {
        int r = sRow[ty * 8 + e];
        float* dst = g_agg + (size_t)r * FDIM + tx * 4;
        float x0, x1, x2, x3;
        unpack2(acc2[e][0], x0, x1);
        unpack2(acc2[e][1], x2, x3);
        red2(dst,     softsignf_(x0 + b2.x), softsignf_(x1 + b2.y));
        red2(dst + 2, softsignf_(x2 + b2.z), softsignf_(x3 + b2.w));
    }
}

// ---------------------------------------------------------------------------
// Node kernel: g = sigmoid([feat, agg, time]); g = sigmoid(g@Wf1+bf1);
//              out = softsign(g@Wf2+bf2)
// ---------------------------------------------------------------------------
__global__ void __launch_bounds__(256, 2)
node_kernel(const float* __restrict__ features,
            const float* __restrict__ time_emb,
            const float* __restrict__ Wf1,
            const float* __restrict__ bf1,
            const float* __restrict__ Wf2,
            const float* __restrict__ bf2,
            float* __restrict__ out)
{
    extern __shared__ float smem[];
    float* sIn = smem;   // TE x LDN floats

    const int tid = threadIdx.x;
    const int tx  = tid & 31;
    const int ty  = tid >> 5;
    const int n0  = blockIdx.x * TE;

    // Gather + first sigmoid applied during smem fill
    for (int n = ty; n < TE; n += 8) {
        int node = n0 + n;
        float4 a, g, t;
        if (node < N_NODES) {
            a = __ldg((const float4*)(features + (size_t)node * FDIM) + tx);
            g = *((const float4*)(g_agg + (size_t)node * FDIM) + tx);
            t = __ldg((const float4*)(time_emb + (size_t)node * FDIM) + tx);
        } else {
            a = g = t = make_float4(0.f, 0.f, 0.f, 0.f);
        }
        *(float4*)&sIn[n * LDN + tx * 4] =
            make_float4(sigmoidf_(a.x), sigmoidf_(a.y), sigmoidf_(a.z), sigmoidf_(a.w));
        *(float4*)&sIn[n * LDN + FDIM + tx * 4] =
            make_float4(sigmoidf_(g.x), sigmoidf_(g.y), sigmoidf_(g.z), sigmoidf_(g.w));
        *(float4*)&sIn[n * LDN + 2 * FDIM + tx * 4] =
            make_float4(sigmoidf_(t.x), sigmoidf_(t.y), sigmoidf_(t.z), sigmoidf_(t.w));
    }
    __syncthreads();

    // ---- GEMM1: [64,384] @ Wf1[384,128], packed f32x2 ----
    u64 acc[8][2];
    #pragma unroll
    for (int e = 0; e < 8; e++) { acc[e][0] = 0ull; acc[e][1] = 0ull; }

    const float* wBase = Wf1 + tx * 4;
    const float* aBase = sIn + (ty * 8) * LDN;

    #pragma unroll 2
    for (int k = 0; k < 3 * FDIM; k += 4) {
        u64 w0a, w0b, w1a, w1b, w2a, w2b, w3a, w3b;
        ldg2x2(wBase + (k + 0) * FDIM, w0a, w0b);
        ldg2x2(wBase + (k + 1) * FDIM, w1a, w1b);
        ldg2x2(wBase + (k + 2) * FDIM, w2a, w2b);
        ldg2x2(wBase + (k + 3) * FDIM, w3a, w3b);
        #pragma unroll
        for (int e = 0; e < 8; e++) {
            float4 a = *(const float4*)(aBase + e * LDN + k);
            u64 a0 = pack2(a.x), a1 = pack2(a.y), a2 = pack2(a.z), a3 = pack2(a.w);
            ffma2(acc[e][0], a0, w0a); ffma2(acc[e][1], a0, w0b);
            ffma2(acc[e][0], a1, w1a); ffma2(acc[e][1], a1, w1b);
            ffma2(acc[e][0], a2, w2a); ffma2(acc[e][1], a2, w2b);
            ffma2(acc[e][0], a3, w3a); ffma2(acc[e][1], a3, w3b);
        }
    }
    __syncthreads();   // reads of sIn done before H overlay

    float4 b1 = __ldg((const float4*)bf1 + tx);
    float* sH = smem;
    #pragma unroll
    for (int e = 0; e < 8; e++) {
        float x0, x1, x2, x3;
        unpack2(acc[e][0], x0, x1);
        unpack2(acc[e][1], x2, x3);
        float4 h;
        h.x = sigmoidf_(x0 + b1.x);
        h.y = sigmoidf_(x1 + b1.y);
        h.z = sigmoidf_(x2 + b1.z);
        h.w = sigmoidf_(x3 + b1.w);
        *(float4*)&sH[(ty * 8 + e) * LDH + tx * 4] = h;
    }
    __syncthreads();

    // ---- GEMM2: [64,128] @ Wf2[128,128], packed f32x2 ----
    u64 acc2[8][2];
    #pragma unroll
    for (int e = 0; e < 8; e++) { acc2[e][0] = 0ull; acc2[e][1] = 0ull; }

    const float* w2Base = Wf2 + tx * 4;
    const float* hBase  = sH + (ty * 8) * LDH;

    #pragma unroll 2
    for (int k = 0; k < FDIM; k += 4) {
        u64 w0a, w0b, w1a, w1b, w2a, w2b, w3a, w3b;
        ldg2x2(w2Base + (k + 0) * FDIM, w0a, w0b);
        ldg2x2(w2Base + (k + 1) * FDIM, w1a, w1b);
        ldg2x2(w2Base + (k + 2) * FDIM, w2a, w2b);
        ldg2x2(w2Base + (k + 3) * FDIM, w3a, w3b);
        #pragma unroll
        for (int e = 0; e < 8; e++) {
            float4 a = *(const float4*)(hBase + e * LDH + k);
            u64 a0 = pack2(a.x), a1 = pack2(a.y), a2 = pack2(a.z), a3 = pack2(a.w);
            ffma2(acc2[e][0], a0, w0a); ffma2(acc2[e][1], a0, w0b);
            ffma2(acc2[e][0], a1, w1a); ffma2(acc2[e][1], a1, w1b);
            ffma2(acc2[e][0], a2, w2a); ffma2(acc2[e][1], a2, w2b);
            ffma2(acc2[e][0], a3, w3a); ffma2(acc2[e][1], a3, w3b);
        }
    }

    float4 b2 = __ldg((const float4*)bf2 + tx);
    #pragma unroll
    for (int e = 0; e < 8; e++) {
        int node = n0 + ty * 8 + e;
        if (node < N_NODES) {
            float x0, x1, x2, x3;
            unpack2(acc2[e][0], x0, x1);
            unpack2(acc2[e][1], x2, x3);
            float4 o;
            o.x = softsignf_(x0 + b2.x);
            o.y = softsignf_(x1 + b2.y);
            o.z = softsignf_(x2 + b2.z);
            o.w = softsignf_(x3 + b2.w);
            *(float4*)(out + (size_t)node * FDIM + tx * 4) = o;
        }
    }
}

extern "C" void kernel_launch(void* const* d_in, const int* in_sizes, int n_in,
                              void* d_out, int out_size)
{
    const float* features = (const float*)d_in[0];
    const int*   rows     = (const int*)  d_in[1];
    const int*   cols     = (const int*)  d_in[2];
    const float* time_emb = (const float*)d_in[3];
    const float* Wm1      = (const float*)d_in[4];
    const float* bm1      = (const float*)d_in[5];
    const float* Wm2      = (const float*)d_in[6];
    const float* bm2      = (const float*)d_in[7];
    const float* Wf1      = (const float*)d_in[8];
    const float* bf1      = (const float*)d_in[9];
    const float* Wf2      = (const float*)d_in[10];
    const float* bf2      = (const float*)d_in[11];
    float* out = (float*)d_out;

    const int edge_smem = TE * LDI * sizeof(float) + 2 * TE * sizeof(int); // 67072 B
    const int node_smem = TE * LDN * sizeof(float);                        // 99328 B
    cudaFuncSetAttribute(edge_kernel, cudaFuncAttributeMaxDynamicSharedMemorySize, edge_smem);
    cudaFuncSetAttribute(node_kernel, cudaFuncAttributeMaxDynamicSharedMemorySize, node_smem);

    void* aggp = nullptr;
    cudaGetSymbolAddress(&aggp, g_agg);
    cudaMemsetAsync(aggp, 0, (size_t)N_NODES * FDIM * sizeof(float));

    edge_kernel<<<N_EDGES / TE, 256, edge_smem>>>(features, rows, cols, Wm1, bm1, Wm2, bm2);
    node_kernel<<<(N_NODES + TE - 1) / TE, 256, node_smem>>>(features, time_emb,
                                                             Wf1, bf1, Wf2, bf2, out);
}

// round 9
// speedup vs baseline: 2.4763x; 1.4931x over previous
#include <cuda_runtime.h>
#include <cuda_bf16.h>
#include <math.h>
#include <stdint.h>

#define N_NODES 10000
#define N_EDGES 640000
#define FDIM    128
#define N_TILES (N_EDGES / 128)   // 5000

#define LDA 264   // smem stride (bf16 elems) for A tile: 256 + 8  (132 words % 32 = 4 -> ldmatrix conflict-free)
#define LDH 136   // smem stride for h tile: 128 + 8

// ---- smem map (bytes) ----
#define SM_ROW   0        // 128 ints
#define SM_B1    512      // 128 floats
#define SM_B2    1024     // 128 floats
#define SM_A     2048
#define SM_ALO   (SM_A + 128 * LDA * 2)        // 69632
#define SM_TOTAL (SM_ALO + 128 * LDA * 2)      // 137216
#define SM_HHI   SM_A                           // overlay after gemm1
#define SM_HLO   (SM_A + 128 * LDH * 2)        // 36864

// ===========================================================================
// Global scratch (no cudaMalloc allowed)
// ===========================================================================
__device__ float g_agg[N_NODES * FDIM];
__device__ __nv_bfloat16 gFhi[N_NODES * FDIM];
__device__ __nv_bfloat16 gFlo[N_NODES * FDIM];
// weight fragments, laid out so each lane ld.global.v2 its mma B-fragment:
// index [frag_id][lane], frag_id = kstep*16 + nfrag  (nfrag over all 128 N)
__device__ uint2 gW1hf[256 * 32];   // Wm1 hi: 16 ksteps x 16 nfrags
__device__ uint2 gW1lf[256 * 32];
__device__ uint2 gW2hf[128 * 32];   // Wm2: 8 ksteps x 16 nfrags
__device__ uint2 gW2lf[128 * 32];

typedef unsigned long long u64;

__device__ __forceinline__ float sigmoidf_(float x) { return 1.0f / (1.0f + __expf(-x)); }
__device__ __forceinline__ float softsignf_(float x) { return x / (1.0f + fabsf(x)); }

__device__ __forceinline__ uint32_t smem_u32(const void* p) {
    uint32_t a;
    asm("{ .reg .u64 t; cvta.to.shared.u64 t, %1; cvt.u32.u64 %0, t; }" : "=r"(a) : "l"(p));
    return a;
}
__device__ __forceinline__ uint32_t pack_bf2(__nv_bfloat16 lo, __nv_bfloat16 hi) {
    __nv_bfloat162 v; v.x = lo; v.y = hi;
    return *(uint32_t*)&v;
}
// d += A(16x16) @ B(16x8), bf16 in, f32 accum  (baseline PTX ISA, sm_80+)
__device__ __forceinline__ void mma_bf16(float4& d, const uint32_t a[4], uint2 b) {
    asm volatile(
        "mma.sync.aligned.m16n8k16.row.col.f32.bf16.bf16.f32 "
        "{%0,%1,%2,%3}, {%4,%5,%6,%7}, {%8,%9}, {%0,%1,%2,%3};"
        : "+f"(d.x), "+f"(d.y), "+f"(d.z), "+f"(d.w)
        : "r"(a[0]), "r"(a[1]), "r"(a[2]), "r"(a[3]), "r"(b.x), "r"(b.y));
}
__device__ __forceinline__ void ldmx4(uint32_t r[4], uint32_t addr) {
    asm volatile("ldmatrix.sync.aligned.m8n8.x4.shared.b16 {%0,%1,%2,%3}, [%4];"
                 : "=r"(r[0]), "=r"(r[1]), "=r"(r[2]), "=r"(r[3]) : "r"(addr));
}
__device__ __forceinline__ void red2(float* p, float v0, float v1) {
    asm volatile("red.global.add.v2.f32 [%0], {%1, %2};" :: "l"(p), "f"(v0), "f"(v1) : "memory");
}
// f32x2 helpers (node kernel, validated R7)
__device__ __forceinline__ void ffma2(u64& d, u64 a, u64 b) {
    asm("fma.rn.f32x2 %0, %1, %2, %0;" : "+l"(d) : "l"(a), "l"(b));
}
__device__ __forceinline__ u64 pack2(float s) {
    u64 r; asm("mov.b64 %0, {%1, %1};" : "=l"(r) : "f"(s)); return r;
}
__device__ __forceinline__ void unpack2(u64 v, float& lo, float& hi) {
    asm("mov.b64 {%0, %1}, %2;" : "=f"(lo), "=f"(hi) : "l"(v));
}
__device__ __forceinline__ void ldg2x2(const float* p, u64& d0, u64& d1) {
    asm("ld.global.nc.v2.b64 {%0, %1}, [%2];" : "=l"(d0), "=l"(d1) : "l"(p));
}

// ===========================================================================
// Prep kernels
// ===========================================================================
__global__ void prep_features(const float* __restrict__ f) {
    int i = blockIdx.x * 256 + threadIdx.x;
    if (i < N_NODES * FDIM) {
        float x = f[i];
        __nv_bfloat16 h = __float2bfloat16_rn(x);
        gFhi[i] = h;
        gFlo[i] = __float2bfloat16_rn(x - __bfloat162float(h));
    }
}
// Build B fragments for W [K x 128] row-major.
// frag_id = kstep*16 + nfrag; element (lane, reg j, half h):
//   n = nfrag*8 + lane/4;  k = kstep*16 + j*8 + (lane%4)*2 + h
__global__ void prep_wfrag(const float* __restrict__ W, int ksteps,
                           uint2* __restrict__ outH, uint2* __restrict__ outL) {
    int i = blockIdx.x * 256 + threadIdx.x;
    if (i >= ksteps * 16 * 32) return;
    int lane = i & 31, fi = i >> 5;
    int kstep = fi >> 4, nfg = fi & 15;
    int n = nfg * 8 + (lane >> 2);
    __nv_bfloat16 hi[2][2], lo[2][2];
    #pragma unroll
    for (int j = 0; j < 2; j++)
        #pragma unroll
        for (int h = 0; h < 2; h++) {
            int k = kstep * 16 + j * 8 + (lane & 3) * 2 + h;
            float x = W[k * 128 + n];
            __nv_bfloat16 xh = __float2bfloat16_rn(x);
            hi[j][h] = xh;
            lo[j][h] = __float2bfloat16_rn(x - __bfloat162float(xh));
        }
    outH[i] = make_uint2(pack_bf2(hi[0][0], hi[0][1]), pack_bf2(hi[1][0], hi[1][1]));
    outL[i] = make_uint2(pack_bf2(lo[0][0], lo[0][1]), pack_bf2(lo[1][0], lo[1][1]));
}

// ===========================================================================
// Edge kernel: persistent, 148 CTAs x 256 threads (8 warps: 4M x 2N).
// Tile = 128 edges x 128 outputs. Split-bf16 mma.sync (3 terms).
// ===========================================================================
__global__ void __launch_bounds__(256, 1)
edge_mma_kernel(const int* __restrict__ rows,
                const int* __restrict__ cols,
                const float* __restrict__ bm1,
                const float* __restrict__ bm2)
{
    extern __shared__ char smem[];
    int*   sRow = (int*)(smem + SM_ROW);
    float* sB1  = (float*)(smem + SM_B1);
    float* sB2  = (float*)(smem + SM_B2);
    __nv_bfloat16* sAhi = (__nv_bfloat16*)(smem + SM_A);
    __nv_bfloat16* sAlo = (__nv_bfloat16*)(smem + SM_ALO);
    __nv_bfloat16* sHhi = (__nv_bfloat16*)(smem + SM_HHI);
    __nv_bfloat16* sHlo = (__nv_bfloat16*)(smem + SM_HLO);

    const int tid  = threadIdx.x;
    const int lane = tid & 31;
    const int wid  = tid >> 5;
    const int wm   = wid & 3;   // M quadrant: rows [wm*32, wm*32+32)
    const int wn   = wid >> 2;  // N half:    cols [wn*64, wn*64+64)
    const uint32_t sb = smem_u32(smem);

    if (tid < 128) { sB1[tid] = __ldg(bm1 + tid); sB2[tid] = __ldg(bm2 + tid); }

    // ldmatrix addressing: lane -> row (lane&15), col-block (lane>>4)*8
    const int arow  = lane & 15;
    const int acolk = (lane >> 4) * 8;
    // accumulator/epilogue coords
    const int erow = lane >> 2;            // + m*16 (+8 for .z/.w)
    const int ecol = (lane & 3) * 2;       // + nf*8 + wn*64

    for (int t = blockIdx.x; t < N_TILES; t += gridDim.x) {
        const int e0 = t * 128;

        // ---- gather split features into smem A ----
        if (tid < 128) sRow[tid] = __ldg(rows + e0 + tid);
        {
            int e = tid >> 1, half = tid & 1;
            int node = half ? __ldg(cols + e0 + e) : __ldg(rows + e0 + e);
            const uint4* srcH = (const uint4*)(gFhi + (size_t)node * FDIM);
            const uint4* srcL = (const uint4*)(gFlo + (size_t)node * FDIM);
            uint4* dstH = (uint4*)(sAhi + e * LDA + half * FDIM);
            uint4* dstL = (uint4*)(sAlo + e * LDA + half * FDIM);
            #pragma unroll
            for (int i = 0; i < 16; i++) {
                dstH[i] = __ldg(srcH + i);
                dstL[i] = __ldg(srcL + i);
            }
        }
        __syncthreads();

        // ---- GEMM1: [128,256] @ W1[256,128], 3-term split bf16 ----
        float4 acc[2][8];
        #pragma unroll
        for (int m = 0; m < 2; m++)
            #pragma unroll
            for (int nf = 0; nf < 8; nf++) acc[m][nf] = make_float4(0.f, 0.f, 0.f, 0.f);

        #pragma unroll 1
        for (int ks = 0; ks < 16; ks++) {
            uint32_t ah[2][4], al[2][4];
            #pragma unroll
            for (int m = 0; m < 2; m++) {
                uint32_t ab = sb + SM_A +
                    (uint32_t)(((wm * 32 + m * 16 + arow) * LDA + ks * 16 + acolk) * 2);
                ldmx4(ah[m], ab);
                ldmx4(al[m], ab + 128 * LDA * 2);
            }
            #pragma unroll
            for (int nf = 0; nf < 8; nf++) {
                int fi = ks * 16 + wn * 8 + nf;
                uint2 bh = __ldg(&gW1hf[fi * 32 + lane]);
                uint2 bl = __ldg(&gW1lf[fi * 32 + lane]);
                #pragma unroll
                for (int m = 0; m < 2; m++) {
                    mma_bf16(acc[m][nf], ah[m], bh);
                    mma_bf16(acc[m][nf], ah[m], bl);
                    mma_bf16(acc[m][nf], al[m], bh);
                }
            }
        }
        __syncthreads();   // all warps done reading sA before sH overlay

        // ---- epilogue 1: h = sigmoid(D1 + bm1) -> split bf16 -> smem ----
        #pragma unroll
        for (int m = 0; m < 2; m++)
            #pragma unroll
            for (int nf = 0; nf < 8; nf++) {
                int r0 = wm * 32 + m * 16 + erow;
                int c  = wn * 64 + nf * 8 + ecol;
                float b0 = sB1[c], b1 = sB1[c + 1];
                float f0 = sigmoidf_(acc[m][nf].x + b0);
                float f1 = sigmoidf_(acc[m][nf].y + b1);
                float f2 = sigmoidf_(acc[m][nf].z + b0);
                float f3 = sigmoidf_(acc[m][nf].w + b1);
                __nv_bfloat16 h0 = __float2bfloat16_rn(f0), h1 = __float2bfloat16_rn(f1);
                __nv_bfloat16 h2 = __float2bfloat16_rn(f2), h3 = __float2bfloat16_rn(f3);
                *(uint32_t*)(sHhi + r0 * LDH + c)       = pack_bf2(h0, h1);
                *(uint32_t*)(sHhi + (r0 + 8) * LDH + c) = pack_bf2(h2, h3);
                *(uint32_t*)(sHlo + r0 * LDH + c) =
                    pack_bf2(__float2bfloat16_rn(f0 - __bfloat162float(h0)),
                             __float2bfloat16_rn(f1 - __bfloat162float(h1)));
                *(uint32_t*)(sHlo + (r0 + 8) * LDH + c) =
                    pack_bf2(__float2bfloat16_rn(f2 - __bfloat162float(h2)),
                             __float2bfloat16_rn(f3 - __bfloat162float(h3)));
            }
        __syncthreads();

        // ---- GEMM2: [128,128] @ W2[128,128] ----
        float4 acc2[2][8];
        #pragma unroll
        for (int m = 0; m < 2; m++)
            #pragma unroll
            for (int nf = 0; nf < 8; nf++) acc2[m][nf] = make_float4(0.f, 0.f, 0.f, 0.f);

        #pragma unroll 1
        for (int ks = 0; ks < 8; ks++) {
            uint32_t ah[2][4], al[2][4];
            #pragma unroll
            for (int m = 0; m < 2; m++) {
                uint32_t ab = sb + SM_HHI +
                    (uint32_t)(((wm * 32 + m * 16 + arow) * LDH + ks * 16 + acolk) * 2);
                ldmx4(ah[m], ab);
                ldmx4(al[m], ab + (SM_HLO - SM_HHI));
            }
            #pragma unroll
            for (int nf = 0; nf < 8; nf++) {
                int fi = ks * 16 + wn * 8 + nf;
                uint2 bh = __ldg(&gW2hf[fi * 32 + lane]);
                uint2 bl = __ldg(&gW2lf[fi * 32 + lane]);
                #pragma unroll
                for (int m = 0; m < 2; m++) {
                    mma_bf16(acc2[m][nf], ah[m], bh);
                    mma_bf16(acc2[m][nf], ah[m], bl);
                    mma_bf16(acc2[m][nf], al[m], bh);
                }
            }
        }

        // ---- epilogue 2: softsign + red scatter into g_agg ----
        #pragma unroll
        for (int m = 0; m < 2; m++) {
            int r0 = wm * 32 + m * 16 + erow;
            int n0 = sRow[r0];
            int n1 = sRow[r0 + 8];
            #pragma unroll
            for (int nf = 0; nf < 8; nf++) {
                int c = wn * 64 + nf * 8 + ecol;
                float b0 = sB2[c], b1 = sB2[c + 1];
                red2(g_agg + (size_t)n0 * FDIM + c,
                     softsignf_(acc2[m][nf].x + b0), softsignf_(acc2[m][nf].y + b1));
                red2(g_agg + (size_t)n1 * FDIM + c,
                     softsignf_(acc2[m][nf].z + b0), softsignf_(acc2[m][nf].w + b1));
            }
        }
        __syncthreads();   // before next tile's gather overwrites sA/sRow
    }
}

// ===========================================================================
// Node kernel (R7 version, unchanged)
// ===========================================================================
#define TEN 64
#define NLDH 132
#define NLDN 388

__global__ void __launch_bounds__(256, 2)
node_kernel(const float* __restrict__ features,
            const float* __restrict__ time_emb,
            const float* __restrict__ Wf1,
            const float* __restrict__ bf1,
            const float* __restrict__ Wf2,
            const float* __restrict__ bf2,
            float* __restrict__ out)
{
    extern __shared__ float smemf[];
    float* sIn = smemf;

    const int tid = threadIdx.x;
    const int tx  = tid & 31;
    const int ty  = tid >> 5;
    const int n0  = blockIdx.x * TEN;

    for (int n = ty; n < TEN; n += 8) {
        int node = n0 + n;
        float4 a, g, t;
        if (node < N_NODES) {
            a = __ldg((const float4*)(features + (size_t)node * FDIM) + tx);
            g = *((const float4*)(g_agg + (size_t)node * FDIM) + tx);
            t = __ldg((const float4*)(time_emb + (size_t)node * FDIM) + tx);
        } else {
            a = g = t = make_float4(0.f, 0.f, 0.f, 0.f);
        }
        *(float4*)&sIn[n * NLDN + tx * 4] =
            make_float4(sigmoidf_(a.x), sigmoidf_(a.y), sigmoidf_(a.z), sigmoidf_(a.w));
        *(float4*)&sIn[n * NLDN + FDIM + tx * 4] =
            make_float4(sigmoidf_(g.x), sigmoidf_(g.y), sigmoidf_(g.z), sigmoidf_(g.w));
        *(float4*)&sIn[n * NLDN + 2 * FDIM + tx * 4] =
            make_float4(sigmoidf_(t.x), sigmoidf_(t.y), sigmoidf_(t.z), sigmoidf_(t.w));
    }
    __syncthreads();

    u64 acc[8][2];
    #pragma unroll
    for (int e = 0; e < 8; e++) { acc[e][0] = 0ull; acc[e][1] = 0ull; }

    const float* wBase = Wf1 + tx * 4;
    const float* aBase = sIn + (ty * 8) * NLDN;

    #pragma unroll 2
    for (int k = 0; k < 3 * FDIM; k += 4) {
        u64 w0a, w0b, w1a, w1b, w2a, w2b, w3a, w3b;
        ldg2x2(wBase + (k + 0) * FDIM, w0a, w0b);
        ldg2x2(wBase + (k + 1) * FDIM, w1a, w1b);
        ldg2x2(wBase + (k + 2) * FDIM, w2a, w2b);
        ldg2x2(wBase + (k + 3) * FDIM, w3a, w3b);
        #pragma unroll
        for (int e = 0; e < 8; e++) {
            float4 a = *(const float4*)(aBase + e * NLDN + k);
            u64 a0 = pack2(a.x), a1 = pack2(a.y), a2 = pack2(a.z), a3 = pack2(a.w);
            ffma2(acc[e][0], a0, w0a); ffma2(acc[e][1], a0, w0b);
            ffma2(acc[e][0], a1, w1a); ffma2(acc[e][1], a1, w1b);
            ffma2(acc[e][0], a2, w2a); ffma2(acc[e][1], a2, w2b);
            ffma2(acc[e][0], a3, w3a); ffma2(acc[e][1], a3, w3b);
        }
    }
    __syncthreads();

    float4 b1 = __ldg((const float4*)bf1 + tx);
    float* sH = smemf;
    #pragma unroll
    for (int e = 0; e < 8; e++) {
        float x0, x1, x2, x3;
        unpack2(acc[e][0], x0, x1);
        unpack2(acc[e][1], x2, x3);
        float4 h;
        h.x = sigmoidf_(x0 + b1.x);
        h.y = sigmoidf_(x1 + b1.y);
        h.z = sigmoidf_(x2 + b1.z);
        h.w = sigmoidf_(x3 + b1.w);
        *(float4*)&sH[(ty * 8 + e) * NLDH + tx * 4] = h;
    }
    __syncthreads();

    u64 acc2[8][2];
    #pragma unroll
    for (int e = 0; e < 8; e++) { acc2[e][0] = 0ull; acc2[e][1] = 0ull; }

    const float* w2Base = Wf2 + tx * 4;
    const float* hBase  = sH + (ty * 8) * NLDH;

    #pragma unroll 2
    for (int k = 0; k < FDIM; k += 4) {
        u64 w0a, w0b, w1a, w1b, w2a, w2b, w3a, w3b;
        ldg2x2(w2Base + (k + 0) * FDIM, w0a, w0b);
        ldg2x2(w2Base + (k + 1) * FDIM, w1a, w1b);
        ldg2x2(w2Base + (k + 2) * FDIM, w2a, w2b);
        ldg2x2(w2Base + (k + 3) * FDIM, w3a, w3b);
        #pragma unroll
        for (int e = 0; e < 8; e++) {
            float4 a = *(const float4*)(hBase + e * NLDH + k);
            u64 a0 = pack2(a.x), a1 = pack2(a.y), a2 = pack2(a.z), a3 = pack2(a.w);
            ffma2(acc2[e][0], a0, w0a); ffma2(acc2[e][1], a0, w0b);
            ffma2(acc2[e][0], a1, w1a); ffma2(acc2[e][1], a1, w1b);
            ffma2(acc2[e][0], a2, w2a); ffma2(acc2[e][1], a2, w2b);
            ffma2(acc2[e][0], a3, w3a); ffma2(acc2[e][1], a3, w3b);
        }
    }

    float4 b2 = __ldg((const float4*)bf2 + tx);
    #pragma unroll
    for (int e = 0; e < 8; e++) {
        int node = n0 + ty * 8 + e;
        if (node < N_NODES) {
            float x0, x1, x2, x3;
            unpack2(acc2[e][0], x0, x1);
            unpack2(acc2[e][1], x2, x3);
            float4 o;
            o.x = softsignf_(x0 + b2.x);
            o.y = softsignf_(x1 + b2.y);
            o.z = softsignf_(x2 + b2.z);
            o.w = softsignf_(x3 + b2.w);
            *(float4*)(out + (size_t)node * FDIM + tx * 4) = o;
        }
    }
}

// ===========================================================================
extern "C" void kernel_launch(void* const* d_in, const int* in_sizes, int n_in,
                              void* d_out, int out_size)
{
    const float* features = (const float*)d_in[0];
    const int*   rows     = (const int*)  d_in[1];
    const int*   cols     = (const int*)  d_in[2];
    const float* time_emb = (const float*)d_in[3];
    const float* Wm1      = (const float*)d_in[4];
    const float* bm1      = (const float*)d_in[5];
    const float* Wm2      = (const float*)d_in[6];
    const float* bm2      = (const float*)d_in[7];
    const float* Wf1      = (const float*)d_in[8];
    const float* bf1      = (const float*)d_in[9];
    const float* Wf2      = (const float*)d_in[10];
    const float* bf2      = (const float*)d_in[11];
    float* out = (float*)d_out;

    const int node_smem = TEN * NLDN * sizeof(float);
    cudaFuncSetAttribute(edge_mma_kernel, cudaFuncAttributeMaxDynamicSharedMemorySize, SM_TOTAL);
    cudaFuncSetAttribute(node_kernel,     cudaFuncAttributeMaxDynamicSharedMemorySize, node_smem);

    void* aggp = nullptr;
    cudaGetSymbolAddress(&aggp, g_agg);
    cudaMemsetAsync(aggp, 0, (size_t)N_NODES * FDIM * sizeof(float));

    uint2 *w1h, *w1l, *w2h, *w2l;
    cudaGetSymbolAddress((void**)&w1h, gW1hf);
    cudaGetSymbolAddress((void**)&w1l, gW1lf);
    cudaGetSymbolAddress((void**)&w2h, gW2hf);
    cudaGetSymbolAddress((void**)&w2l, gW2lf);

    prep_features<<<(N_NODES * FDIM + 255) / 256, 256>>>(features);
    prep_wfrag<<<32, 256>>>(Wm1, 16, w1h, w1l);
    prep_wfrag<<<16, 256>>>(Wm2,  8, w2h, w2l);

    edge_mma_kernel<<<148, 256, SM_TOTAL>>>(rows, cols, bm1, bm2);

    node_kernel<<<(N_NODES + TEN - 1) / TEN, 256, node_smem>>>(features, time_emb,
                                                               Wf1, bf1, Wf2, bf2, out);
}